// round 9
// baseline (speedup 1.0000x reference)
#include <cuda_runtime.h>
#include <cstdint>

// LayerNorm backward fused: golden_x [B,S,H], golden_gamma [H], golden_beta [H]
// B=4, S=4096, H=2048, fp32. Output layout: [x | gamma | beta] concatenated.
// R8: warp-specialized TMA bulk pipeline. 8 consumer warps + 1 producer warp.
//     Producer streams rows (dy,x1,x2) into a 4-stage smem ring via
//     cp.async.bulk + mbarrier; consumers reduce with a named barrier.
//     Producer is never stalled by consumer barriers -> continuous DRAM demand.

#define HF 2048
#define ROWS 16384
#define CONSUMERS 256        // 8 warps
#define THREADS 288          // + 1 producer warp
#define GRID 296             // 148 SMs * 2 CTAs/SM
#define NST 4
#define STAGE_FLOATS (3 * HF)
#define STAGE_BYTES (STAGE_FLOATS * 4)        // 24576
#define DYN_SMEM (NST * STAGE_BYTES)          // 98304

#define MBAR_INIT(addr, cnt) \
    asm volatile("mbarrier.init.shared.b64 [%0], %1;" :: "r"(addr), "r"(cnt) : "memory")
#define MBAR_ARRIVE(addr) \
    asm volatile("mbarrier.arrive.shared.b64 _, [%0];" :: "r"(addr) : "memory")
#define MBAR_EXPECT_TX(addr, bytes) \
    asm volatile("mbarrier.arrive.expect_tx.shared.b64 _, [%0], %1;" :: "r"(addr), "r"(bytes) : "memory")

#define MBAR_WAIT(addr, parity) do {                                          \
    uint32_t _mb = (addr); uint32_t _ph = (parity); uint32_t _done;           \
    asm volatile("{\n\t.reg .pred p;\n\t"                                     \
        "mbarrier.try_wait.parity.acquire.cta.shared::cta.b64 p, [%1], %2;\n\t" \
        "selp.b32 %0, 1, 0, p;\n\t}"                                          \
        : "=r"(_done) : "r"(_mb), "r"(_ph) : "memory");                       \
    if (!_done) {                                                             \
        asm volatile("{\n\t.reg .pred P1;\n\t"                                \
            "WL_%=:\n\t"                                                      \
            "mbarrier.try_wait.parity.acquire.cta.shared::cta.b64 P1, [%0], %1, 0x989680;\n\t" \
            "@P1 bra.uni WD_%=;\n\t"                                          \
            "bra.uni WL_%=;\n\t"                                              \
            "WD_%=:\n\t}" :: "r"(_mb), "r"(_ph) : "memory");                  \
    }                                                                         \
} while (0)

__device__ __forceinline__ void bulk_cp(uint32_t dst, const void* src,
                                        uint32_t bytes, uint32_t mbar) {
    asm volatile(
        "cp.async.bulk.shared::cluster.global.mbarrier::complete_tx::bytes "
        "[%0], [%1], %2, [%3];"
        :: "r"(dst), "l"(src), "r"(bytes), "r"(mbar) : "memory");
}

__global__ __launch_bounds__(THREADS, 2) void ln_bwd_kernel(
    const float* __restrict__ dy,
    const float* __restrict__ x1,
    const float* __restrict__ x2,
    const float* __restrict__ rstd,
    const float* __restrict__ mean,
    const float* __restrict__ gamma,
    const float* __restrict__ dsum,
    float* __restrict__ out)
{
    extern __shared__ float ring[];                       // [NST][3][HF]
    __shared__ float red[2][3][8];
    __shared__ __align__(8) unsigned long long mbar_full[NST];
    __shared__ __align__(8) unsigned long long mbar_empty[NST];

    const int tid  = threadIdx.x;
    const int lane = tid & 31;
    const int wid  = tid >> 5;          // 0..8
    const int bid  = blockIdx.x;

    uint32_t fb[NST], eb[NST];
    #pragma unroll
    for (int s = 0; s < NST; s++) {
        fb[s] = (uint32_t)__cvta_generic_to_shared(&mbar_full[s]);
        eb[s] = (uint32_t)__cvta_generic_to_shared(&mbar_empty[s]);
    }

    if (tid == 0) {
        #pragma unroll
        for (int s = 0; s < NST; s++) {
            MBAR_INIT(fb[s], 1);     // producer expect_tx; completion by tx bytes
            MBAR_INIT(eb[s], 8);     // 8 consumer-warp arrivals
        }
    }
    // fused zeroing of the dgamma/dbeta region (2*HF floats). All 296 CTAs
    // co-resident; earliest flush atomic is ~10^5 cycles away.
    if (bid < 16 && tid < 256) {
        out[(size_t)ROWS * HF + bid * 256 + tid] = 0.0f;
        __threadfence();
    }
    __syncthreads();

    if (wid == 8) {
        // ================= producer warp =================
        if (lane == 0) {
            const uint32_t ring_u32 = (uint32_t)__cvta_generic_to_shared(ring);
            int slot = 0, phase = 1;                 // first empty-wait passes
            for (int row = bid; row < ROWS; row += GRID) {
                MBAR_WAIT(eb[slot], phase);
                const size_t gb = (size_t)row * HF;
                const uint32_t db = ring_u32 + slot * STAGE_BYTES;
                MBAR_EXPECT_TX(fb[slot], STAGE_BYTES);
                bulk_cp(db,                 dy + gb, HF * 4, fb[slot]);
                bulk_cp(db + HF * 4,        x1 + gb, HF * 4, fb[slot]);
                bulk_cp(db + 2 * HF * 4,    x2 + gb, HF * 4, fb[slot]);
                if (++slot == NST) { slot = 0; phase ^= 1; }
            }
        }
    } else {
        // ================= consumer warps (0..7) =================
        const int c0 = 4 * tid;          // 0..1020
        const int c1 = c0 + HF / 2;      // 1024..2044

        const float4 g0 = *(const float4*)(gamma + c0);
        const float4 g1 = *(const float4*)(gamma + c1);
        float gv[8] = {g0.x, g0.y, g0.z, g0.w, g1.x, g1.y, g1.z, g1.w};

        float ag[8] = {0.f, 0.f, 0.f, 0.f, 0.f, 0.f, 0.f, 0.f};
        float ab[8] = {0.f, 0.f, 0.f, 0.f, 0.f, 0.f, 0.f, 0.f};
        const float inv_d = 1.0f / (float)HF;

        float Pmu = __ldcs(mean + bid);
        float Prs = __ldcs(rstd + bid);

        int slot = 0, phase = 0, par = 0;
        for (int row = bid; row < ROWS; row += GRID) {
            const size_t base = (size_t)row * HF;

            // dsum for THIS row: in flight through the full-wait + reduction
            const float4 ds0 = __ldcs((const float4*)(dsum + base + c0));
            const float4 ds1 = __ldcs((const float4*)(dsum + base + c1));
            const float mu = Pmu, rs = Prs;
            // next row's scalars
            if (row + GRID < ROWS) {
                Pmu = __ldcs(mean + row + GRID);
                Prs = __ldcs(rstd + row + GRID);
            }

            MBAR_WAIT(fb[slot], phase);

            const float* st = ring + slot * STAGE_FLOATS;
            const float4 dy0 = *(const float4*)(st + c0);
            const float4 dy1 = *(const float4*)(st + c1);
            const float4 a0  = *(const float4*)(st + HF + c0);
            const float4 a1  = *(const float4*)(st + HF + c1);
            const float4 b0  = *(const float4*)(st + 2 * HF + c0);
            const float4 b1  = *(const float4*)(st + 2 * HF + c1);

            float dyv[8] = {dy0.x, dy0.y, dy0.z, dy0.w,
                            dy1.x, dy1.y, dy1.z, dy1.w};
            float xh[8]  = {a0.x + b0.x - mu, a0.y + b0.y - mu,
                            a0.z + b0.z - mu, a0.w + b0.w - mu,
                            a1.x + b1.x - mu, a1.y + b1.y - mu,
                            a1.z + b1.z - mu, a1.w + b1.w - mu};

            float s1 = 0.f, s2 = 0.f, s3 = 0.f;
            #pragma unroll
            for (int k = 0; k < 8; k++) {
                const float pdxl = dyv[k] * gv[k];
                s1 = fmaf(pdxl, xh[k], s1);
                s2 += pdxl;
                s3 += xh[k];
            }
            // all smem values consumed into registers (s1/s2/s3 depend on all
            // 24 loaded floats) -> safe to release the slot to the producer
            if (lane == 0) MBAR_ARRIVE(eb[slot]);
            if (++slot == NST) { slot = 0; phase ^= 1; }

            #pragma unroll
            for (int off = 16; off > 0; off >>= 1) {
                s1 += __shfl_xor_sync(0xFFFFFFFFu, s1, off);
                s2 += __shfl_xor_sync(0xFFFFFFFFu, s2, off);
                s3 += __shfl_xor_sync(0xFFFFFFFFu, s3, off);
            }
            if (lane == 0) {
                red[par][0][wid] = s1;
                red[par][1][wid] = s2;
                red[par][2][wid] = s3;
            }
            asm volatile("bar.sync 1, %0;" :: "n"(CONSUMERS) : "memory");
            float t1 = 0.f, t2 = 0.f, t3 = 0.f;
            #pragma unroll
            for (int w = 0; w < 8; w++) {
                t1 += red[par][0][w];
                t2 += red[par][1][w];
                t3 += red[par][2][w];
            }
            par ^= 1;

            const float rs3     = rs * rs * rs;
            const float pd_var  = -0.5f * t1 * rs3;
            const float pd_mean = -t2 * rs + pd_var * (-2.0f * inv_d) * t3;
            const float coef    = pd_var * (2.0f * inv_d);
            const float cmean   = pd_mean * inv_d;

            float ov[8];
            #pragma unroll
            for (int k = 0; k < 8; k++) {
                const float pdxl = dyv[k] * gv[k];
                ov[k] = fmaf(pdxl, rs, fmaf(coef, xh[k], cmean));
                ag[k] = fmaf(dyv[k] * xh[k], rs, ag[k]);
                ab[k] += dyv[k];
            }
            ov[0] += ds0.x; ov[1] += ds0.y; ov[2] += ds0.z; ov[3] += ds0.w;
            ov[4] += ds1.x; ov[5] += ds1.y; ov[6] += ds1.z; ov[7] += ds1.w;

            __stcs((float4*)(out + base + c0),
                   make_float4(ov[0], ov[1], ov[2], ov[3]));
            __stcs((float4*)(out + base + c1),
                   make_float4(ov[4], ov[5], ov[6], ov[7]));
        }

        // flush dgamma/dbeta partials
        float* gout = out + (size_t)ROWS * HF;
        float* bout = gout + HF;
        #pragma unroll
        for (int k = 0; k < 4; k++) {
            atomicAdd(gout + c0 + k, ag[k]);
            atomicAdd(gout + c1 + k, ag[4 + k]);
            atomicAdd(bout + c0 + k, ab[k]);
            atomicAdd(bout + c1 + k, ab[4 + k]);
        }
    }
}

extern "C" void kernel_launch(void* const* d_in, const int* in_sizes, int n_in,
                              void* d_out, int out_size) {
    const float* dy    = (const float*)d_in[0];
    const float* x1    = (const float*)d_in[1];
    const float* x2    = (const float*)d_in[2];
    const float* rstd  = (const float*)d_in[3];
    const float* mean  = (const float*)d_in[4];
    const float* gamma = (const float*)d_in[5];
    const float* dsum  = (const float*)d_in[6];
    float* out = (float*)d_out;

    static bool attr_set = false;
    if (!attr_set) {
        cudaFuncSetAttribute(ln_bwd_kernel,
                             cudaFuncAttributeMaxDynamicSharedMemorySize, DYN_SMEM);
        attr_set = true;
    }

    ln_bwd_kernel<<<GRID, THREADS, DYN_SMEM>>>(dy, x1, x2, rstd, mean, gamma, dsum, out);
}

// round 10
// speedup vs baseline: 1.0689x; 1.0689x over previous
#include <cuda_runtime.h>

// LayerNorm backward fused: golden_x [B,S,H], golden_gamma [H], golden_beta [H]
// B=4, S=4096, H=2048, fp32. Output layout: [x | gamma | beta] concatenated.
// R9: R5 main kernel UNCHANGED (2 CTAs/SM x 256 thr, 8 cols/thread,
//     distance-2 double-buffered register prefetch, 127 regs, DRAM 76.6%).
//     zero_param_grads kernel replaced by cudaMemsetAsync (cheaper graph node).

#define HF 2048
#define ROWS 16384           // B*S
#define THREADS 256
#define GRID 296             // 148 SMs * 2 CTAs/SM

__global__ __launch_bounds__(THREADS, 2) void ln_bwd_kernel(
    const float* __restrict__ dy,
    const float* __restrict__ x1,
    const float* __restrict__ x2,
    const float* __restrict__ rstd,
    const float* __restrict__ mean,
    const float* __restrict__ gamma,
    const float* __restrict__ dsum,
    float* __restrict__ out)
{
    __shared__ float red[2][3][8];

    const int tid  = threadIdx.x;
    const int lane = tid & 31;
    const int wid  = tid >> 5;
    const int bid  = blockIdx.x;

    const int c0 = 4 * tid;          // 0..1020
    const int c1 = c0 + HF / 2;      // 1024..2044

    const float4 g0 = *(const float4*)(gamma + c0);
    const float4 g1 = *(const float4*)(gamma + c1);
    float gv[8] = {g0.x, g0.y, g0.z, g0.w, g1.x, g1.y, g1.z, g1.w};

    float ag[8] = {0.f, 0.f, 0.f, 0.f, 0.f, 0.f, 0.f, 0.f};
    float ab[8] = {0.f, 0.f, 0.f, 0.f, 0.f, 0.f, 0.f, 0.f};

    const float inv_d = 1.0f / (float)HF;

    // ---- two register buffer sets: dy, x1, x2 (+ mean/rstd scalars) ----
    float4 Ady0, Ady1, Aa0, Aa1, Ab0, Ab1; float Amu = 0.f, Ars = 0.f;
    float4 Bdy0, Bdy1, Ba0, Ba1, Bb0, Bb1; float Bmu = 0.f, Brs = 0.f;

    #define LOADBUF(P, row)                                                  \
        if ((row) < ROWS) {                                                  \
            const size_t _b = (size_t)(row) * HF;                            \
            P##dy0 = __ldcs((const float4*)(dy + _b + c0));                  \
            P##dy1 = __ldcs((const float4*)(dy + _b + c1));                  \
            P##a0  = __ldcs((const float4*)(x1 + _b + c0));                  \
            P##a1  = __ldcs((const float4*)(x1 + _b + c1));                  \
            P##b0  = __ldcs((const float4*)(x2 + _b + c0));                  \
            P##b1  = __ldcs((const float4*)(x2 + _b + c1));                  \
            P##mu  = __ldcs(mean + (row));                                   \
            P##rs  = __ldcs(rstd + (row));                                   \
        }

    // Consume buffer P (row `row`), refill P for row `nrow`, do full row work.
    #define STEP(P, row, nrow, PAR)                                          \
    {                                                                        \
        const size_t base = (size_t)(row) * HF;                              \
        /* consume buffer into locals (frees P for the refill below) */      \
        float dyv[8] = {P##dy0.x, P##dy0.y, P##dy0.z, P##dy0.w,              \
                        P##dy1.x, P##dy1.y, P##dy1.z, P##dy1.w};             \
        const float mu = P##mu;                                              \
        const float rs = P##rs;                                              \
        float xh[8]  = {P##a0.x + P##b0.x - mu, P##a0.y + P##b0.y - mu,      \
                        P##a0.z + P##b0.z - mu, P##a0.w + P##b0.w - mu,      \
                        P##a1.x + P##b1.x - mu, P##a1.y + P##b1.y - mu,      \
                        P##a1.z + P##b1.z - mu, P##a1.w + P##b1.w - mu};     \
        /* dsum for THIS row: issued now, consumed post-barrier */           \
        const float4 ds0 = __ldcs((const float4*)(dsum + base + c0));        \
        const float4 ds1 = __ldcs((const float4*)(dsum + base + c1));        \
        /* refill buffer: distance-2 prefetch */                             \
        LOADBUF(P, nrow);                                                    \
        /* local partial sums */                                             \
        float s1 = 0.f, s2 = 0.f, s3 = 0.f;                                  \
        _Pragma("unroll")                                                    \
        for (int k = 0; k < 8; k++) {                                        \
            const float pdxl = dyv[k] * gv[k];                               \
            s1 = fmaf(pdxl, xh[k], s1);                                      \
            s2 += pdxl;                                                      \
            s3 += xh[k];                                                     \
        }                                                                    \
        _Pragma("unroll")                                                    \
        for (int off = 16; off > 0; off >>= 1) {                             \
            s1 += __shfl_xor_sync(0xFFFFFFFFu, s1, off);                     \
            s2 += __shfl_xor_sync(0xFFFFFFFFu, s2, off);                     \
            s3 += __shfl_xor_sync(0xFFFFFFFFu, s3, off);                     \
        }                                                                    \
        if (lane == 0) {                                                     \
            red[PAR][0][wid] = s1;                                           \
            red[PAR][1][wid] = s2;                                           \
            red[PAR][2][wid] = s3;                                           \
        }                                                                    \
        __syncthreads();                                                     \
        float t1 = 0.f, t2 = 0.f, t3 = 0.f;                                  \
        _Pragma("unroll")                                                    \
        for (int w = 0; w < 8; w++) {                                        \
            t1 += red[PAR][0][w];                                            \
            t2 += red[PAR][1][w];                                            \
            t3 += red[PAR][2][w];                                            \
        }                                                                    \
        const float rs3     = rs * rs * rs;                                  \
        const float pd_var  = -0.5f * t1 * rs3;                              \
        const float pd_mean = -t2 * rs + pd_var * (-2.0f * inv_d) * t3;      \
        const float coef    = pd_var * (2.0f * inv_d);                       \
        const float cmean   = pd_mean * inv_d;                               \
        float ov[8];                                                         \
        _Pragma("unroll")                                                    \
        for (int k = 0; k < 8; k++) {                                        \
            const float pdxl = dyv[k] * gv[k];                               \
            ov[k] = fmaf(pdxl, rs, fmaf(coef, xh[k], cmean));                \
            ag[k] = fmaf(dyv[k] * xh[k], rs, ag[k]);                         \
            ab[k] += dyv[k];                                                 \
        }                                                                    \
        ov[0] += ds0.x; ov[1] += ds0.y; ov[2] += ds0.z; ov[3] += ds0.w;      \
        ov[4] += ds1.x; ov[5] += ds1.y; ov[6] += ds1.z; ov[7] += ds1.w;      \
        __stcs((float4*)(out + base + c0),                                   \
               make_float4(ov[0], ov[1], ov[2], ov[3]));                     \
        __stcs((float4*)(out + base + c1),                                   \
               make_float4(ov[4], ov[5], ov[6], ov[7]));                     \
    }

    // ---- prologue: rows bid (A) and bid+GRID (B) in flight ----
    LOADBUF(A, bid);
    LOADBUF(B, bid + GRID);

    int par = 0;
    for (int r = bid; r < ROWS; r += 2 * GRID) {
        STEP(A, r, r + 2 * GRID, par); par ^= 1;
        if (r + GRID < ROWS) {
            STEP(B, r + GRID, r + 3 * GRID, par); par ^= 1;
        }
    }

    // flush dgamma/dbeta partials: 296 CTAs * 4096 atomics -> negligible
    float* gout = out + (size_t)ROWS * HF;
    float* bout = gout + HF;
    #pragma unroll
    for (int k = 0; k < 4; k++) {
        atomicAdd(gout + c0 + k, ag[k]);
        atomicAdd(gout + c1 + k, ag[4 + k]);
        atomicAdd(bout + c0 + k, ab[k]);
        atomicAdd(bout + c1 + k, ab[4 + k]);
    }
}

extern "C" void kernel_launch(void* const* d_in, const int* in_sizes, int n_in,
                              void* d_out, int out_size) {
    const float* dy    = (const float*)d_in[0];
    const float* x1    = (const float*)d_in[1];
    const float* x2    = (const float*)d_in[2];
    const float* rstd  = (const float*)d_in[3];
    const float* mean  = (const float*)d_in[4];
    const float* gamma = (const float*)d_in[5];
    const float* dsum  = (const float*)d_in[6];
    float* out = (float*)d_out;

    // zero the dgamma/dbeta region (2*HF floats) via a memset node:
    // cheaper than a kernel launch, graph-capturable, no alloc/free.
    cudaMemsetAsync(out + (size_t)ROWS * HF, 0, 2 * HF * sizeof(float));

    ln_bwd_kernel<<<GRID, THREADS>>>(dy, x1, x2, rstd, mean, gamma, dsum, out);
}